// round 7
// baseline (speedup 1.0000x reference)
#include <cuda_runtime.h>
#include <cstdint>

#define Bb   4
#define Tt   12
#define Nn   512
#define DIMM 128
#define DK   32
#define ROWS (Bb*Tt*Nn)          // 24576

// ---------------- scratch ----------------
__device__ float g_Q[ROWS * DIMM];
__device__ float g_K[ROWS * DIMM];
__device__ float g_V[ROWS * DIMM];
__device__ float g_X[ROWS * DIMM];

// ---------------- helpers ----------------
__device__ __forceinline__ float f2tf32(float x) {
    unsigned u;
    asm("cvt.rna.tf32.f32 %0, %1;" : "=r"(u) : "f"(x));
    return __uint_as_float(u);
}
__device__ __forceinline__ unsigned f2tf32u(float x) {
    unsigned u;
    asm("cvt.rna.tf32.f32 %0, %1;" : "=r"(u) : "f"(x));
    return u;
}

__device__ __forceinline__ void mma8(float* c,
                                     unsigned a0, unsigned a1, unsigned a2, unsigned a3,
                                     unsigned b0, unsigned b1) {
    asm volatile(
        "mma.sync.aligned.m16n8k8.row.col.f32.tf32.tf32.f32 "
        "{%0,%1,%2,%3}, {%4,%5,%6,%7}, {%8,%9}, {%0,%1,%2,%3};"
        : "+f"(c[0]), "+f"(c[1]), "+f"(c[2]), "+f"(c[3])
        : "r"(a0), "r"(a1), "r"(a2), "r"(a3), "r"(b0), "r"(b1));
}

// perm within each 8-wide k-group: orig col d -> 2*(d&3) + ((d>>2)&1)

// ================= GEMM (k-split staging, 2 CTAs/SM) — unchanged =================
#define GS 72
#define SMEM_GEMM (2 * 128 * GS * 4)

__global__ __launch_bounds__(256, 2)
void gemm_tc(const float* __restrict__ x0, const float* __restrict__ w0,
             const float* __restrict__ bb0, float* __restrict__ y0,
             const float* __restrict__ x1, const float* __restrict__ w1,
             const float* __restrict__ bb1, float* __restrict__ y1,
             const float* __restrict__ x2, const float* __restrict__ w2,
             const float* __restrict__ bb2, float* __restrict__ y2)
{
    extern __shared__ float sm[];
    float* Xs = sm;               // [128][72]
    float* Ws = sm + 128 * GS;    // [128][72]

    const float* X = x0; const float* W = w0; const float* bias = bb0; float* Y = y0;
    if (blockIdx.y == 1) { X = x1; W = w1; bias = bb1; Y = y1; }
    else if (blockIdx.y == 2) { X = x2; W = w2; bias = bb2; Y = y2; }

    const int tid = threadIdx.x, lane = tid & 31, w = tid >> 5;
    const int g = lane >> 2, t = lane & 3;
    const size_t row0 = (size_t)blockIdx.x * 128;

    const int mrow0 = (w >> 1) * 32;
    const int e0    = (w & 1) * 64;

    float acc[2][8][4];
    #pragma unroll
    for (int mt = 0; mt < 2; mt++)
        #pragma unroll
        for (int nt = 0; nt < 8; nt++)
            #pragma unroll
            for (int c = 0; c < 4; c++) acc[mt][nt][c] = 0.f;

    for (int kh = 0; kh < 2; kh++) {
        if (kh) __syncthreads();
        #pragma unroll
        for (int i = 0; i < 8; i++) {
            int idx = i * 256 + tid;
            int r = idx >> 4, c4 = idx & 15;
            float4 xv = *(const float4*)(X + (row0 + r) * DIMM + kh * 64 + c4 * 4);
            float4 wv = *(const float4*)(W + (size_t)r * DIMM + kh * 64 + c4 * 4);
            int kb = c4 * 4;
            int base = kb & ~7, off = (kb & 4) ? 1 : 0;
            float* xd = Xs + r * GS + base + off;
            xd[0] = f2tf32(xv.x); xd[2] = f2tf32(xv.y);
            xd[4] = f2tf32(xv.z); xd[6] = f2tf32(xv.w);
            float* wd = Ws + r * GS + base + off;
            wd[0] = f2tf32(wv.x); wd[2] = f2tf32(wv.y);
            wd[4] = f2tf32(wv.z); wd[6] = f2tf32(wv.w);
        }
        __syncthreads();

        #pragma unroll
        for (int ks = 0; ks < 8; ks++) {
            uint2 aL[2], aH[2];
            #pragma unroll
            for (int mt = 0; mt < 2; mt++) {
                const float* ap = Xs + (mrow0 + 16 * mt + g) * GS + ks * 8 + 2 * t;
                aL[mt] = *(const uint2*)ap;
                aH[mt] = *(const uint2*)(ap + 8 * GS);
            }
            #pragma unroll
            for (int nt = 0; nt < 8; nt++) {
                uint2 b = *(const uint2*)(Ws + (e0 + 8 * nt + g) * GS + ks * 8 + 2 * t);
                mma8(acc[0][nt], aL[0].x, aH[0].x, aL[0].y, aH[0].y, b.x, b.y);
                mma8(acc[1][nt], aL[1].x, aH[1].x, aL[1].y, aH[1].y, b.x, b.y);
            }
        }
    }

    #pragma unroll
    for (int nt = 0; nt < 8; nt++) {
        float2 bv = *(const float2*)(bias + e0 + 8 * nt + 2 * t);
        #pragma unroll
        for (int mt = 0; mt < 2; mt++) {
            size_t r0 = row0 + mrow0 + 16 * mt + g;
            float2 o0 = make_float2(acc[mt][nt][0] + bv.x, acc[mt][nt][1] + bv.y);
            float2 o1 = make_float2(acc[mt][nt][2] + bv.x, acc[mt][nt][3] + bv.y);
            *(float2*)(Y + r0 * DIMM + e0 + 8 * nt + 2 * t) = o0;
            *(float2*)(Y + (r0 + 8) * DIMM + e0 + 8 * nt + 2 * t) = o1;
        }
    }
}

// ================= Flash attention (tf32, double-buffered KV, deferred mask) =========
#define QSS 40
#define KSS 40
#define VSS 72
#define OFF_KS0 5120
#define OFF_KS1 7680
#define OFF_VT0 10240
#define OFF_VT1 12544
#define SMEM_ATTN (14848 * 4)   // 59392 B -> 2 CTAs/SM

__global__ __launch_bounds__(256, 2)
void attn_tc(const float* __restrict__ Q, const float* __restrict__ K,
             const float* __restrict__ V, const int* __restrict__ mask,
             const float* __restrict__ adjm, float* __restrict__ Xo)
{
    extern __shared__ float sm[];
    float* Qs = sm;                                   // [128][40]
    float* KsB[2] = { sm + OFF_KS0, sm + OFF_KS1 };   // [64][40] x2
    float* VtB[2] = { sm + OFF_VT0, sm + OFF_VT1 };   // [32][72] x2

    const int tid = threadIdx.x, lane = tid & 31, w = tid >> 5;
    const int g = lane >> 2, t = lane & 3;

    const int bid = blockIdx.x;
    const int h  = bid & 3;
    const int qp = (bid >> 2) & 3;
    const int bt = bid >> 4;
    const size_t nb = (size_t)bt * Nn;
    const int n0 = qp * 128;

    // staging indices (fixed per thread): iter i covers row ri = i*32 + (tid>>3)
    const int sr  = tid >> 3;       // 0..31
    const int sc4 = tid & 7;        // 0..7
    const int skb   = sc4 * 4;
    const int sbase = skb & ~7, soff = (skb & 4) ? 1 : 0;
    const int skvp0 = 2 * (sr & 3) + ((sr >> 2) & 1);   // kv-perm within 8-group (row part)

    // ---- stage Q block ----
    #pragma unroll
    for (int i = 0; i < 4; i++) {
        int idx = i * 256 + tid;
        int r = idx >> 3, c4 = idx & 7;
        float4 qv = *(const float4*)(Q + (nb + n0 + r) * DIMM + h * DK + c4 * 4);
        int kb = c4 * 4, base = kb & ~7, off = (kb & 4) ? 1 : 0;
        float* qd = Qs + r * QSS + base + off;
        qd[0] = f2tf32(qv.x); qd[2] = f2tf32(qv.y);
        qd[4] = f2tf32(qv.z); qd[6] = f2tf32(qv.w);
    }

    // ---- prologue: stage chunk 0 into buffer 0 ----
    {
        float* Ks = KsB[0];
        float* Vt = VtB[0];
        #pragma unroll
        for (int i = 0; i < 2; i++) {
            int r = i * 32 + sr;
            float4 kv = *(const float4*)(K + (nb + r) * DIMM + h * DK + sc4 * 4);
            float* kd = Ks + r * KSS + sbase + soff;
            kd[0] = f2tf32(kv.x); kd[2] = f2tf32(kv.y);
            kd[4] = f2tf32(kv.z); kd[6] = f2tf32(kv.w);
            float4 vv = *(const float4*)(V + (nb + r) * DIMM + h * DK + sc4 * 4);
            int kvp = (r >> 3) * 8 + skvp0;
            Vt[(skb + 0) * VSS + kvp] = f2tf32(vv.x);
            Vt[(skb + 1) * VSS + kvp] = f2tf32(vv.y);
            Vt[(skb + 2) * VSS + kvp] = f2tf32(vv.z);
            Vt[(skb + 3) * VSS + kvp] = f2tf32(vv.w);
        }
    }
    __syncthreads();

    float oacc[4][4];
    #pragma unroll
    for (int nt = 0; nt < 4; nt++)
        #pragma unroll
        for (int c = 0; c < 4; c++) oacc[nt][c] = 0.f;

    float m0 = -1e30f, m1 = -1e30f, l0 = 0.f, l1 = 0.f;

    const int qrow0 = n0 + 16 * w + g;
    const size_t mrb0 = (nb + qrow0) * (size_t)Nn;
    const size_t mrb1 = mrb0 + 8 * (size_t)Nn;

    // shfl source lanes for PV A-frag construction
    const int s0 = 4 * g + (t >> 1);
    const int s1 = s0 + 2;
    const bool todd = (t & 1);

    const float scale = 0.17677669529663687f;

    for (int c = 0; c < 8; c++) {
        float* Ks = KsB[c & 1];
        float* Vt = VtB[c & 1];
        float* Ksn = KsB[(c + 1) & 1];
        float* Vtn = VtB[(c + 1) & 1];

        // ---- issue K/V gmem loads for chunk c+1 (consumed at STS below) ----
        float4 kreg[2], vreg[2];
        if (c < 7) {
            #pragma unroll
            for (int i = 0; i < 2; i++) {
                int r = (c + 1) * 64 + i * 32 + sr;
                kreg[i] = *(const float4*)(K + (nb + r) * DIMM + h * DK + sc4 * 4);
                vreg[i] = *(const float4*)(V + (nb + r) * DIMM + h * DK + sc4 * 4);
            }
        }

        // ---- issue mask/adjm loads for chunk c (consumed post-exp) ----
        int2  mk0[8], mk1[8];
        float2 ad0[8], ad1[8];
        const int colb = c * 64 + 2 * t;
        #pragma unroll
        for (int nt = 0; nt < 8; nt++) {
            int col = colb + 8 * nt;
            mk0[nt] = *(const int2*)  (mask + mrb0 + col);
            mk1[nt] = *(const int2*)  (mask + mrb1 + col);
            ad0[nt] = *(const float2*)(adjm + mrb0 + col);
            ad1[nt] = *(const float2*)(adjm + mrb1 + col);
        }

        // ---- S = Q Kc^T (from current buffer) ----
        float sacc[8][4];
        #pragma unroll
        for (int nt = 0; nt < 8; nt++)
            #pragma unroll
            for (int cc = 0; cc < 4; cc++) sacc[nt][cc] = 0.f;

        #pragma unroll
        for (int ks = 0; ks < 4; ks++) {
            const float* ap = Qs + (16 * w + g) * QSS + ks * 8 + 2 * t;
            uint2 aL = *(const uint2*)ap;
            uint2 aH = *(const uint2*)(ap + 8 * QSS);
            #pragma unroll
            for (int nt = 0; nt < 8; nt++) {
                uint2 b = *(const uint2*)(Ks + (8 * nt + g) * KSS + ks * 8 + 2 * t);
                mma8(sacc[nt], aL.x, aH.x, aL.y, aH.y, b.x, b.y);
            }
        }

        // ---- STS chunk c+1 into the other buffer (LDG data arrived under MMA) ----
        if (c < 7) {
            #pragma unroll
            for (int i = 0; i < 2; i++) {
                int r = i * 32 + sr;
                float* kd = Ksn + r * KSS + sbase + soff;
                kd[0] = f2tf32(kreg[i].x); kd[2] = f2tf32(kreg[i].y);
                kd[4] = f2tf32(kreg[i].z); kd[6] = f2tf32(kreg[i].w);
                int kvp = (r >> 3) * 8 + skvp0;
                Vtn[(skb + 0) * VSS + kvp] = f2tf32(vreg[i].x);
                Vtn[(skb + 1) * VSS + kvp] = f2tf32(vreg[i].y);
                Vtn[(skb + 2) * VSS + kvp] = f2tf32(vreg[i].z);
                Vtn[(skb + 3) * VSS + kvp] = f2tf32(vreg[i].w);
            }
        }

        // ---- row max over RAW scores (mask deferred; cancels exactly) ----
        float rmax0 = -1e30f, rmax1 = -1e30f;
        #pragma unroll
        for (int nt = 0; nt < 8; nt++) {
            float v0 = sacc[nt][0] * scale;
            float v1 = sacc[nt][1] * scale;
            float v2 = sacc[nt][2] * scale;
            float v3 = sacc[nt][3] * scale;
            sacc[nt][0] = v0; sacc[nt][1] = v1; sacc[nt][2] = v2; sacc[nt][3] = v3;
            rmax0 = fmaxf(rmax0, fmaxf(v0, v1));
            rmax1 = fmaxf(rmax1, fmaxf(v2, v3));
        }
        rmax0 = fmaxf(rmax0, __shfl_xor_sync(0xffffffffu, rmax0, 1));
        rmax0 = fmaxf(rmax0, __shfl_xor_sync(0xffffffffu, rmax0, 2));
        rmax1 = fmaxf(rmax1, __shfl_xor_sync(0xffffffffu, rmax1, 1));
        rmax1 = fmaxf(rmax1, __shfl_xor_sync(0xffffffffu, rmax1, 2));

        float nm0 = fmaxf(m0, rmax0), nm1 = fmaxf(m1, rmax1);
        float al0 = __expf(m0 - nm0), al1 = __expf(m1 - nm1);
        m0 = nm0; m1 = nm1;

        // ---- P = (mask ? 0 : exp(s-m)) * adjm, kept in registers ----
        unsigned pa[8][4];
        float rs0 = 0.f, rs1 = 0.f;
        #pragma unroll
        for (int nt = 0; nt < 8; nt++) {
            float e0 = __expf(sacc[nt][0] - nm0);
            float e1 = __expf(sacc[nt][1] - nm0);
            float e2 = __expf(sacc[nt][2] - nm1);
            float e3 = __expf(sacc[nt][3] - nm1);
            if (mk0[nt].x) e0 = 0.f;
            if (mk0[nt].y) e1 = 0.f;
            if (mk1[nt].x) e2 = 0.f;
            if (mk1[nt].y) e3 = 0.f;
            rs0 += e0 + e1; rs1 += e2 + e3;
            pa[nt][0] = f2tf32u(e0 * ad0[nt].x);   // P[g   ][2t  ]
            pa[nt][1] = f2tf32u(e1 * ad0[nt].y);   // P[g   ][2t+1]
            pa[nt][2] = f2tf32u(e2 * ad1[nt].x);   // P[g+8 ][2t  ]
            pa[nt][3] = f2tf32u(e3 * ad1[nt].y);   // P[g+8 ][2t+1]
        }
        rs0 += __shfl_xor_sync(0xffffffffu, rs0, 1);
        rs0 += __shfl_xor_sync(0xffffffffu, rs0, 2);
        rs1 += __shfl_xor_sync(0xffffffffu, rs1, 1);
        rs1 += __shfl_xor_sync(0xffffffffu, rs1, 2);
        l0 = l0 * al0 + rs0;
        l1 = l1 * al1 + rs1;

        #pragma unroll
        for (int nt = 0; nt < 4; nt++) {
            oacc[nt][0] *= al0; oacc[nt][1] *= al0;
            oacc[nt][2] *= al1; oacc[nt][3] *= al1;
        }

        // ---- O += P Vc : A-frags via lane shuffles ----
        #pragma unroll
        for (int kb = 0; kb < 8; kb++) {
            unsigned x0 = __shfl_sync(0xffffffffu, pa[kb][0], s0);
            unsigned x1 = __shfl_sync(0xffffffffu, pa[kb][1], s0);
            unsigned y0 = __shfl_sync(0xffffffffu, pa[kb][2], s0);
            unsigned y1 = __shfl_sync(0xffffffffu, pa[kb][3], s0);
            unsigned z0 = __shfl_sync(0xffffffffu, pa[kb][0], s1);
            unsigned z1 = __shfl_sync(0xffffffffu, pa[kb][1], s1);
            unsigned w0 = __shfl_sync(0xffffffffu, pa[kb][2], s1);
            unsigned w1 = __shfl_sync(0xffffffffu, pa[kb][3], s1);
            unsigned a0 = todd ? x1 : x0;   // P[g   ][8kb + t  ]
            unsigned a1 = todd ? y1 : y0;   // P[g+8 ][8kb + t  ]
            unsigned a2 = todd ? z1 : z0;   // P[g   ][8kb + t+4]
            unsigned a3 = todd ? w1 : w0;   // P[g+8 ][8kb + t+4]
            #pragma unroll
            for (int nt = 0; nt < 4; nt++) {
                uint2 b = *(const uint2*)(Vt + (8 * nt + g) * VSS + kb * 8 + 2 * t);
                mma8(oacc[nt], a0, a1, a2, a3, b.x, b.y);
            }
        }

        __syncthreads();   // chunk c+1 staging visible; buffer c reusable
    }

    // ---- epilogue ----
    float inv0 = 1.f / l0, inv1 = 1.f / l1;
    #pragma unroll
    for (int nt = 0; nt < 4; nt++) {
        float2 o0 = make_float2(oacc[nt][0] * inv0, oacc[nt][1] * inv0);
        float2 o1 = make_float2(oacc[nt][2] * inv1, oacc[nt][3] * inv1);
        *(float2*)(Xo + (nb + qrow0) * DIMM + h * DK + 8 * nt + 2 * t) = o0;
        *(float2*)(Xo + (nb + qrow0 + 8) * DIMM + h * DK + 8 * nt + 2 * t) = o1;
    }
}

// ---------------- launcher ----------------
extern "C" void kernel_launch(void* const* d_in, const int* in_sizes, int n_in,
                              void* d_out, int out_size)
{
    const float* query = (const float*)d_in[0];
    const float* key   = (const float*)d_in[1];
    const float* value = (const float*)d_in[2];
    const int*   mask  = (const int*)  d_in[3];
    const float* adjm  = (const float*)d_in[4];
    const float* Wq    = (const float*)d_in[5];
    const float* bq    = (const float*)d_in[6];
    const float* Wk    = (const float*)d_in[7];
    const float* bk    = (const float*)d_in[8];
    const float* Wv    = (const float*)d_in[9];
    const float* bv    = (const float*)d_in[10];
    const float* Wp    = (const float*)d_in[11];
    const float* bp    = (const float*)d_in[12];

    float *pQ, *pK, *pV, *pX;
    cudaGetSymbolAddress((void**)&pQ, g_Q);
    cudaGetSymbolAddress((void**)&pK, g_K);
    cudaGetSymbolAddress((void**)&pV, g_V);
    cudaGetSymbolAddress((void**)&pX, g_X);

    cudaFuncSetAttribute(gemm_tc, cudaFuncAttributeMaxDynamicSharedMemorySize, SMEM_GEMM);
    cudaFuncSetAttribute(attn_tc, cudaFuncAttributeMaxDynamicSharedMemorySize, SMEM_ATTN);

    gemm_tc<<<dim3(ROWS / 128, 3), 256, SMEM_GEMM>>>(
        query, Wq, bq, pQ,
        key,   Wk, bk, pK,
        value, Wv, bv, pV);

    attn_tc<<<Bb * Tt * 4 * 4, 256, SMEM_ATTN>>>(pQ, pK, pV, mask, adjm, pX);

    gemm_tc<<<dim3(ROWS / 128, 1), 256, SMEM_GEMM>>>(
        pX, Wp, bp, (float*)d_out,
        pX, Wp, bp, (float*)d_out,
        pX, Wp, bp, (float*)d_out);
}

// round 9
// speedup vs baseline: 1.2071x; 1.2071x over previous
#include <cuda_runtime.h>
#include <cstdint>

#define Bb   4
#define Tt   12
#define Nn   512
#define DIMM 128
#define DK   32
#define ROWS (Bb*Tt*Nn)          // 24576

// ---------------- scratch ----------------
__device__ float g_Q[ROWS * DIMM];
__device__ float g_K[ROWS * DIMM];
__device__ float g_V[ROWS * DIMM];
__device__ float g_X[ROWS * DIMM];

// ---------------- helpers ----------------
__device__ __forceinline__ float f2tf32(float x) {
    unsigned u;
    asm("cvt.rna.tf32.f32 %0, %1;" : "=r"(u) : "f"(x));
    return __uint_as_float(u);
}
__device__ __forceinline__ unsigned f2tf32u(float x) {
    unsigned u;
    asm("cvt.rna.tf32.f32 %0, %1;" : "=r"(u) : "f"(x));
    return u;
}

__device__ __forceinline__ void mma8(float* c,
                                     unsigned a0, unsigned a1, unsigned a2, unsigned a3,
                                     unsigned b0, unsigned b1) {
    asm volatile(
        "mma.sync.aligned.m16n8k8.row.col.f32.tf32.tf32.f32 "
        "{%0,%1,%2,%3}, {%4,%5,%6,%7}, {%8,%9}, {%0,%1,%2,%3};"
        : "+f"(c[0]), "+f"(c[1]), "+f"(c[2]), "+f"(c[3])
        : "r"(a0), "r"(a1), "r"(a2), "r"(a3), "r"(b0), "r"(b1));
}

// perm within each 8-wide k-group: orig col d -> 2*(d&3) + ((d>>2)&1)

// ================= GEMM (k-split staging, 2 CTAs/SM) — unchanged =================
#define GS 72
#define SMEM_GEMM (2 * 128 * GS * 4)

__global__ __launch_bounds__(256, 2)
void gemm_tc(const float* __restrict__ x0, const float* __restrict__ w0,
             const float* __restrict__ bb0, float* __restrict__ y0,
             const float* __restrict__ x1, const float* __restrict__ w1,
             const float* __restrict__ bb1, float* __restrict__ y1,
             const float* __restrict__ x2, const float* __restrict__ w2,
             const float* __restrict__ bb2, float* __restrict__ y2)
{
    extern __shared__ float sm[];
    float* Xs = sm;               // [128][72]
    float* Ws = sm + 128 * GS;    // [128][72]

    const float* X = x0; const float* W = w0; const float* bias = bb0; float* Y = y0;
    if (blockIdx.y == 1) { X = x1; W = w1; bias = bb1; Y = y1; }
    else if (blockIdx.y == 2) { X = x2; W = w2; bias = bb2; Y = y2; }

    const int tid = threadIdx.x, lane = tid & 31, w = tid >> 5;
    const int g = lane >> 2, t = lane & 3;
    const size_t row0 = (size_t)blockIdx.x * 128;

    const int mrow0 = (w >> 1) * 32;
    const int e0    = (w & 1) * 64;

    float acc[2][8][4];
    #pragma unroll
    for (int mt = 0; mt < 2; mt++)
        #pragma unroll
        for (int nt = 0; nt < 8; nt++)
            #pragma unroll
            for (int c = 0; c < 4; c++) acc[mt][nt][c] = 0.f;

    for (int kh = 0; kh < 2; kh++) {
        if (kh) __syncthreads();
        #pragma unroll
        for (int i = 0; i < 8; i++) {
            int idx = i * 256 + tid;
            int r = idx >> 4, c4 = idx & 15;
            float4 xv = *(const float4*)(X + (row0 + r) * DIMM + kh * 64 + c4 * 4);
            float4 wv = *(const float4*)(W + (size_t)r * DIMM + kh * 64 + c4 * 4);
            int kb = c4 * 4;
            int base = kb & ~7, off = (kb & 4) ? 1 : 0;
            float* xd = Xs + r * GS + base + off;
            xd[0] = f2tf32(xv.x); xd[2] = f2tf32(xv.y);
            xd[4] = f2tf32(xv.z); xd[6] = f2tf32(xv.w);
            float* wd = Ws + r * GS + base + off;
            wd[0] = f2tf32(wv.x); wd[2] = f2tf32(wv.y);
            wd[4] = f2tf32(wv.z); wd[6] = f2tf32(wv.w);
        }
        __syncthreads();

        #pragma unroll
        for (int ks = 0; ks < 8; ks++) {
            uint2 aL[2], aH[2];
            #pragma unroll
            for (int mt = 0; mt < 2; mt++) {
                const float* ap = Xs + (mrow0 + 16 * mt + g) * GS + ks * 8 + 2 * t;
                aL[mt] = *(const uint2*)ap;
                aH[mt] = *(const uint2*)(ap + 8 * GS);
            }
            #pragma unroll
            for (int nt = 0; nt < 8; nt++) {
                uint2 b = *(const uint2*)(Ws + (e0 + 8 * nt + g) * GS + ks * 8 + 2 * t);
                mma8(acc[0][nt], aL[0].x, aH[0].x, aL[0].y, aH[0].y, b.x, b.y);
                mma8(acc[1][nt], aL[1].x, aH[1].x, aL[1].y, aH[1].y, b.x, b.y);
            }
        }
    }

    #pragma unroll
    for (int nt = 0; nt < 8; nt++) {
        float2 bv = *(const float2*)(bias + e0 + 8 * nt + 2 * t);
        #pragma unroll
        for (int mt = 0; mt < 2; mt++) {
            size_t r0 = row0 + mrow0 + 16 * mt + g;
            float2 o0 = make_float2(acc[mt][nt][0] + bv.x, acc[mt][nt][1] + bv.y);
            float2 o1 = make_float2(acc[mt][nt][2] + bv.x, acc[mt][nt][3] + bv.y);
            *(float2*)(Y + r0 * DIMM + e0 + 8 * nt + 2 * t) = o0;
            *(float2*)(Y + (r0 + 8) * DIMM + e0 + 8 * nt + 2 * t) = o1;
        }
    }
}

// ================= Flash attention (tf32, 4-warp CTAs, 5 CTAs/SM) =================
// CTA: 128 thr, 64 q-rows; grid 1536 = 48 bt x 8 qp x 4 h.
// R6 math exactly (mask pre-max, adjm post-mask, P in regs via shuffles),
// with P stored in-place into sacc to cut register pressure.
#define QSS 40
#define KSS 40
#define VSS 72
#define OFF_KS 2560
#define OFF_VT 5120
#define SMEM_ATTN ((OFF_VT + 32 * VSS) * 4)   // 29696 B

__global__ __launch_bounds__(128, 5)
void attn_tc(const float* __restrict__ Q, const float* __restrict__ K,
             const float* __restrict__ V, const int* __restrict__ mask,
             const float* __restrict__ adjm, float* __restrict__ Xo)
{
    extern __shared__ float sm[];
    float* Qs = sm;             // [64][40]
    float* Ks = sm + OFF_KS;    // [64][40]
    float* Vt = sm + OFF_VT;    // [32][72]

    const int tid = threadIdx.x, lane = tid & 31, w = tid >> 5;   // w in 0..3
    const int g = lane >> 2, t = lane & 3;

    const int bid = blockIdx.x;
    const int h  = bid & 3;
    const int qp = (bid >> 2) & 7;
    const int bt = bid >> 5;
    const size_t nb = (size_t)bt * Nn;
    const int n0 = qp * 64;

    // ---- stage Q block (64x32) ----
    #pragma unroll
    for (int i = 0; i < 4; i++) {
        int idx = i * 128 + tid;
        int r = idx >> 3, c4 = idx & 7;
        float4 qv = *(const float4*)(Q + (nb + n0 + r) * DIMM + h * DK + c4 * 4);
        int kb = c4 * 4, base = kb & ~7, off = (kb & 4) ? 1 : 0;
        float* qd = Qs + r * QSS + base + off;
        qd[0] = f2tf32(qv.x); qd[2] = f2tf32(qv.y);
        qd[4] = f2tf32(qv.z); qd[6] = f2tf32(qv.w);
    }

    float oacc[4][4];
    #pragma unroll
    for (int nt = 0; nt < 4; nt++)
        #pragma unroll
        for (int c = 0; c < 4; c++) oacc[nt][c] = 0.f;

    float m0 = -1e30f, m1 = -1e30f, l0 = 0.f, l1 = 0.f;

    const int qrow0 = n0 + 16 * w + g;
    const size_t mrb0 = (nb + qrow0) * (size_t)Nn;
    const size_t mrb1 = mrb0 + 8 * (size_t)Nn;

    // shfl source lanes for PV A-frag construction
    const int s0 = 4 * g + (t >> 1);
    const int s1 = s0 + 2;
    const bool todd = (t & 1);

    const float scale = 0.17677669529663687f;

    for (int c = 0; c < 8; c++) {
        __syncthreads();
        // ---- stage K chunk (64x32, permuted) and V chunk (transposed, kv-permuted) ----
        #pragma unroll
        for (int i = 0; i < 4; i++) {
            int idx = i * 128 + tid;
            int r = idx >> 3, c4 = idx & 7;
            float4 kv = *(const float4*)(K + (nb + c * 64 + r) * DIMM + h * DK + c4 * 4);
            int kb = c4 * 4, base = kb & ~7, off = (kb & 4) ? 1 : 0;
            float* kd = Ks + r * KSS + base + off;
            kd[0] = f2tf32(kv.x); kd[2] = f2tf32(kv.y);
            kd[4] = f2tf32(kv.z); kd[6] = f2tf32(kv.w);
            float4 vv = *(const float4*)(V + (nb + c * 64 + r) * DIMM + h * DK + c4 * 4);
            int kvp = (r >> 3) * 8 + 2 * (r & 3) + ((r >> 2) & 1);
            Vt[(kb + 0) * VSS + kvp] = f2tf32(vv.x);
            Vt[(kb + 1) * VSS + kvp] = f2tf32(vv.y);
            Vt[(kb + 2) * VSS + kvp] = f2tf32(vv.z);
            Vt[(kb + 3) * VSS + kvp] = f2tf32(vv.w);
        }
        __syncthreads();

        // ---- prefetch mask ----
        int2 mk0[8], mk1[8];
        const int colb = c * 64 + 2 * t;
        #pragma unroll
        for (int nt = 0; nt < 8; nt++) {
            int col = colb + 8 * nt;
            mk0[nt] = *(const int2*)(mask + mrb0 + col);
            mk1[nt] = *(const int2*)(mask + mrb1 + col);
        }

        // ---- S = Q Kc^T ----
        float sacc[8][4];
        #pragma unroll
        for (int nt = 0; nt < 8; nt++)
            #pragma unroll
            for (int cc = 0; cc < 4; cc++) sacc[nt][cc] = 0.f;

        #pragma unroll
        for (int ks = 0; ks < 4; ks++) {
            const float* ap = Qs + (16 * w + g) * QSS + ks * 8 + 2 * t;
            uint2 aL = *(const uint2*)ap;
            uint2 aH = *(const uint2*)(ap + 8 * QSS);
            #pragma unroll
            for (int nt = 0; nt < 8; nt++) {
                uint2 b = *(const uint2*)(Ks + (8 * nt + g) * KSS + ks * 8 + 2 * t);
                mma8(sacc[nt], aL.x, aH.x, aL.y, aH.y, b.x, b.y);
            }
        }

        // ---- mask + row max; adjm loads issued as mask regs die ----
        float rmax0 = -1e30f, rmax1 = -1e30f;
        float2 ad0[8], ad1[8];
        #pragma unroll
        for (int nt = 0; nt < 8; nt++) {
            float v0 = sacc[nt][0] * scale; if (mk0[nt].x) v0 = -1e9f;
            float v1 = sacc[nt][1] * scale; if (mk0[nt].y) v1 = -1e9f;
            float v2 = sacc[nt][2] * scale; if (mk1[nt].x) v2 = -1e9f;
            float v3 = sacc[nt][3] * scale; if (mk1[nt].y) v3 = -1e9f;
            sacc[nt][0] = v0; sacc[nt][1] = v1; sacc[nt][2] = v2; sacc[nt][3] = v3;
            rmax0 = fmaxf(rmax0, fmaxf(v0, v1));
            rmax1 = fmaxf(rmax1, fmaxf(v2, v3));
            int col = colb + 8 * nt;
            ad0[nt] = *(const float2*)(adjm + mrb0 + col);
            ad1[nt] = *(const float2*)(adjm + mrb1 + col);
        }
        rmax0 = fmaxf(rmax0, __shfl_xor_sync(0xffffffffu, rmax0, 1));
        rmax0 = fmaxf(rmax0, __shfl_xor_sync(0xffffffffu, rmax0, 2));
        rmax1 = fmaxf(rmax1, __shfl_xor_sync(0xffffffffu, rmax1, 1));
        rmax1 = fmaxf(rmax1, __shfl_xor_sync(0xffffffffu, rmax1, 2));

        float nm0 = fmaxf(m0, rmax0), nm1 = fmaxf(m1, rmax1);
        float al0 = __expf(m0 - nm0), al1 = __expf(m1 - nm1);
        m0 = nm0; m1 = nm1;

        // ---- P = exp(S-m)*adjm, stored IN-PLACE into sacc (tf32 bits) ----
        float rs0 = 0.f, rs1 = 0.f;
        #pragma unroll
        for (int nt = 0; nt < 8; nt++) {
            float p0 = __expf(sacc[nt][0] - nm0);
            float p1 = __expf(sacc[nt][1] - nm0);
            float p2 = __expf(sacc[nt][2] - nm1);
            float p3 = __expf(sacc[nt][3] - nm1);
            rs0 += p0 + p1; rs1 += p2 + p3;
            sacc[nt][0] = __uint_as_float(f2tf32u(p0 * ad0[nt].x));   // P[g   ][2t  ]
            sacc[nt][1] = __uint_as_float(f2tf32u(p1 * ad0[nt].y));   // P[g   ][2t+1]
            sacc[nt][2] = __uint_as_float(f2tf32u(p2 * ad1[nt].x));   // P[g+8 ][2t  ]
            sacc[nt][3] = __uint_as_float(f2tf32u(p3 * ad1[nt].y));   // P[g+8 ][2t+1]
        }
        rs0 += __shfl_xor_sync(0xffffffffu, rs0, 1);
        rs0 += __shfl_xor_sync(0xffffffffu, rs0, 2);
        rs1 += __shfl_xor_sync(0xffffffffu, rs1, 1);
        rs1 += __shfl_xor_sync(0xffffffffu, rs1, 2);
        l0 = l0 * al0 + rs0;
        l1 = l1 * al1 + rs1;

        #pragma unroll
        for (int nt = 0; nt < 4; nt++) {
            oacc[nt][0] *= al0; oacc[nt][1] *= al0;
            oacc[nt][2] *= al1; oacc[nt][3] *= al1;
        }

        // ---- O += P Vc : A-frags via lane shuffles (P bits live in sacc) ----
        #pragma unroll
        for (int kb = 0; kb < 8; kb++) {
            unsigned x0 = __shfl_sync(0xffffffffu, __float_as_uint(sacc[kb][0]), s0);
            unsigned x1 = __shfl_sync(0xffffffffu, __float_as_uint(sacc[kb][1]), s0);
            unsigned y0 = __shfl_sync(0xffffffffu, __float_as_uint(sacc[kb][2]), s0);
            unsigned y1 = __shfl_sync(0xffffffffu, __float_as_uint(sacc[kb][3]), s0);
            unsigned z0 = __shfl_sync(0xffffffffu, __float_as_uint(sacc[kb][0]), s1);
            unsigned z1 = __shfl_sync(0xffffffffu, __float_as_uint(sacc[kb][1]), s1);
            unsigned w0 = __shfl_sync(0xffffffffu, __float_as_uint(sacc[kb][2]), s1);
            unsigned w1 = __shfl_sync(0xffffffffu, __float_as_uint(sacc[kb][3]), s1);
            unsigned a0 = todd ? x1 : x0;   // P[g   ][8kb + t  ]
            unsigned a1 = todd ? y1 : y0;   // P[g+8 ][8kb + t  ]
            unsigned a2 = todd ? z1 : z0;   // P[g   ][8kb + t+4]
            unsigned a3 = todd ? w1 : w0;   // P[g+8 ][8kb + t+4]
            #pragma unroll
            for (int nt = 0; nt < 4; nt++) {
                uint2 b = *(const uint2*)(Vt + (8 * nt + g) * VSS + kb * 8 + 2 * t);
                mma8(oacc[nt], a0, a1, a2, a3, b.x, b.y);
            }
        }
    }

    // ---- epilogue ----
    float inv0 = 1.f / l0, inv1 = 1.f / l1;
    #pragma unroll
    for (int nt = 0; nt < 4; nt++) {
        float2 o0 = make_float2(oacc[nt][0] * inv0, oacc[nt][1] * inv0);
        float2 o1 = make_float2(oacc[nt][2] * inv1, oacc[nt][3] * inv1);
        *(float2*)(Xo + (nb + qrow0) * DIMM + h * DK + 8 * nt + 2 * t) = o0;
        *(float2*)(Xo + (nb + qrow0 + 8) * DIMM + h * DK + 8 * nt + 2 * t) = o1;
    }
}

// ---------------- launcher ----------------
extern "C" void kernel_launch(void* const* d_in, const int* in_sizes, int n_in,
                              void* d_out, int out_size)
{
    const float* query = (const float*)d_in[0];
    const float* key   = (const float*)d_in[1];
    const float* value = (const float*)d_in[2];
    const int*   mask  = (const int*)  d_in[3];
    const float* adjm  = (const float*)d_in[4];
    const float* Wq    = (const float*)d_in[5];
    const float* bq    = (const float*)d_in[6];
    const float* Wk    = (const float*)d_in[7];
    const float* bk    = (const float*)d_in[8];
    const float* Wv    = (const float*)d_in[9];
    const float* bv    = (const float*)d_in[10];
    const float* Wp    = (const float*)d_in[11];
    const float* bp    = (const float*)d_in[12];

    float *pQ, *pK, *pV, *pX;
    cudaGetSymbolAddress((void**)&pQ, g_Q);
    cudaGetSymbolAddress((void**)&pK, g_K);
    cudaGetSymbolAddress((void**)&pV, g_V);
    cudaGetSymbolAddress((void**)&pX, g_X);

    cudaFuncSetAttribute(gemm_tc, cudaFuncAttributeMaxDynamicSharedMemorySize, SMEM_GEMM);
    cudaFuncSetAttribute(attn_tc, cudaFuncAttributeMaxDynamicSharedMemorySize, SMEM_ATTN);

    gemm_tc<<<dim3(ROWS / 128, 3), 256, SMEM_GEMM>>>(
        query, Wq, bq, pQ,
        key,   Wk, bk, pK,
        value, Wv, bv, pV);

    attn_tc<<<Bb * Tt * 8 * 4, 128, SMEM_ATTN>>>(pQ, pK, pV, mask, adjm, pX);

    gemm_tc<<<dim3(ROWS / 128, 1), 256, SMEM_GEMM>>>(
        pX, Wp, bp, (float*)d_out,
        pX, Wp, bp, (float*)d_out,
        pX, Wp, bp, (float*)d_out);
}

// round 10
// speedup vs baseline: 1.4191x; 1.1757x over previous
#include <cuda_runtime.h>
#include <cstdint>

#define Bb   4
#define Tt   12
#define Nn   512
#define DIMM 128
#define DK   32
#define ROWS (Bb*Tt*Nn)          // 24576

// ---------------- scratch ----------------
__device__ float g_Q[ROWS * DIMM];           // tf32-rounded, [row][dim]
__device__ float g_K[ROWS * DIMM];           // tf32-rounded, [row][dim]
__device__ float g_V[ROWS * DIMM];           // tf32-rounded, TRANSPOSED [bt][h][d][kv]
__device__ float g_X[ROWS * DIMM];           // fp32 attn output

// ---------------- helpers ----------------
__device__ __forceinline__ float f2tf32(float x) {
    unsigned u;
    asm("cvt.rna.tf32.f32 %0, %1;" : "=r"(u) : "f"(x));
    return __uint_as_float(u);
}
__device__ __forceinline__ unsigned f2tf32u(float x) {
    unsigned u;
    asm("cvt.rna.tf32.f32 %0, %1;" : "=r"(u) : "f"(x));
    return u;
}

__device__ __forceinline__ void mma8(float* c,
                                     unsigned a0, unsigned a1, unsigned a2, unsigned a3,
                                     unsigned b0, unsigned b1) {
    asm volatile(
        "mma.sync.aligned.m16n8k8.row.col.f32.tf32.tf32.f32 "
        "{%0,%1,%2,%3}, {%4,%5,%6,%7}, {%8,%9}, {%0,%1,%2,%3};"
        : "+f"(c[0]), "+f"(c[1]), "+f"(c[2]), "+f"(c[3])
        : "r"(a0), "r"(a1), "r"(a2), "r"(a3), "r"(b0), "r"(b1));
}

__device__ __forceinline__ void cpa16(unsigned dst, const void* src) {
    asm volatile("cp.async.cg.shared.global [%0], [%1], 16;" :: "r"(dst), "l"(src));
}
#define CP_COMMIT() asm volatile("cp.async.commit_group;")
#define CP_WAIT0()  asm volatile("cp.async.wait_group 0;")

// ================= GEMM (k-split staging, 2 CTAs/SM) =================
// mode 0: plain fp32 out; mode 1: tf32-rounded out; mode 2: tf32-rounded + V-transposed out
#define GS 72
#define SMEM_GEMM (2 * 128 * GS * 4)

__global__ __launch_bounds__(256, 2)
void gemm_tc(const float* __restrict__ x0, const float* __restrict__ w0,
             const float* __restrict__ bb0, float* __restrict__ y0,
             const float* __restrict__ x1, const float* __restrict__ w1,
             const float* __restrict__ bb1, float* __restrict__ y1,
             const float* __restrict__ x2, const float* __restrict__ w2,
             const float* __restrict__ bb2, float* __restrict__ y2,
             int md0, int md1, int md2)
{
    extern __shared__ float sm[];
    float* Xs = sm;               // [128][72]
    float* Ws = sm + 128 * GS;    // [128][72]

    const float* X = x0; const float* W = w0; const float* bias = bb0; float* Y = y0;
    int mode = md0;
    if (blockIdx.y == 1) { X = x1; W = w1; bias = bb1; Y = y1; mode = md1; }
    else if (blockIdx.y == 2) { X = x2; W = w2; bias = bb2; Y = y2; mode = md2; }

    const int tid = threadIdx.x, lane = tid & 31, w = tid >> 5;
    const int g = lane >> 2, t = lane & 3;
    const size_t row0 = (size_t)blockIdx.x * 128;

    const int mrow0 = (w >> 1) * 32;
    const int e0    = (w & 1) * 64;

    float acc[2][8][4];
    #pragma unroll
    for (int mt = 0; mt < 2; mt++)
        #pragma unroll
        for (int nt = 0; nt < 8; nt++)
            #pragma unroll
            for (int c = 0; c < 4; c++) acc[mt][nt][c] = 0.f;

    for (int kh = 0; kh < 2; kh++) {
        if (kh) __syncthreads();
        #pragma unroll
        for (int i = 0; i < 8; i++) {
            int idx = i * 256 + tid;
            int r = idx >> 4, c4 = idx & 15;
            float4 xv = *(const float4*)(X + (row0 + r) * DIMM + kh * 64 + c4 * 4);
            float4 wv = *(const float4*)(W + (size_t)r * DIMM + kh * 64 + c4 * 4);
            int kb = c4 * 4;
            int base = kb & ~7, off = (kb & 4) ? 1 : 0;
            float* xd = Xs + r * GS + base + off;
            xd[0] = f2tf32(xv.x); xd[2] = f2tf32(xv.y);
            xd[4] = f2tf32(xv.z); xd[6] = f2tf32(xv.w);
            float* wd = Ws + r * GS + base + off;
            wd[0] = f2tf32(wv.x); wd[2] = f2tf32(wv.y);
            wd[4] = f2tf32(wv.z); wd[6] = f2tf32(wv.w);
        }
        __syncthreads();

        #pragma unroll
        for (int ks = 0; ks < 8; ks++) {
            uint2 aL[2], aH[2];
            #pragma unroll
            for (int mt = 0; mt < 2; mt++) {
                const float* ap = Xs + (mrow0 + 16 * mt + g) * GS + ks * 8 + 2 * t;
                aL[mt] = *(const uint2*)ap;
                aH[mt] = *(const uint2*)(ap + 8 * GS);
            }
            #pragma unroll
            for (int nt = 0; nt < 8; nt++) {
                uint2 b = *(const uint2*)(Ws + (e0 + 8 * nt + g) * GS + ks * 8 + 2 * t);
                mma8(acc[0][nt], aL[0].x, aH[0].x, aL[0].y, aH[0].y, b.x, b.y);
                mma8(acc[1][nt], aL[1].x, aH[1].x, aL[1].y, aH[1].y, b.x, b.y);
            }
        }
    }

    #pragma unroll
    for (int nt = 0; nt < 8; nt++) {
        float2 bv = *(const float2*)(bias + e0 + 8 * nt + 2 * t);
        const int e = e0 + 8 * nt + 2 * t;
        #pragma unroll
        for (int mt = 0; mt < 2; mt++) {
            size_t r0 = row0 + mrow0 + 16 * mt + g;
            float v00 = acc[mt][nt][0] + bv.x, v01 = acc[mt][nt][1] + bv.y;
            float v10 = acc[mt][nt][2] + bv.x, v11 = acc[mt][nt][3] + bv.y;
            if (mode == 0) {
                *(float2*)(Y + r0 * DIMM + e) = make_float2(v00, v01);
                *(float2*)(Y + (r0 + 8) * DIMM + e) = make_float2(v10, v11);
            } else if (mode == 1) {
                *(float2*)(Y + r0 * DIMM + e) = make_float2(f2tf32(v00), f2tf32(v01));
                *(float2*)(Y + (r0 + 8) * DIMM + e) = make_float2(f2tf32(v10), f2tf32(v11));
            } else {
                // V transposed: [bt][h][d][kv], h = e>>5, d = e&31, kv = row&511
                int bt = (int)(r0 >> 9);
                int kv = (int)(r0 & 511);
                int dl = e & 31;
                size_t base = ((size_t)(bt * 4 + (e >> 5)) * 32) * 512;
                Y[base + (size_t)dl * 512 + kv]           = f2tf32(v00);
                Y[base + (size_t)(dl + 1) * 512 + kv]     = f2tf32(v01);
                Y[base + (size_t)dl * 512 + kv + 8]       = f2tf32(v10);
                Y[base + (size_t)(dl + 1) * 512 + kv + 8] = f2tf32(v11);
            }
        }
    }
}

// ================= Flash attention (tf32, cp.async double-buffered) =================
// CTA: 128 thr (4 warps), 64 q-rows; grid 1536 = 48 bt x 8 qp x 4 h. 4 CTAs/SM.
// Natural smem layouts, scalar LDS.32 fragment loads (conflict-free: strides ≡4 mod 32).
#define QS2 36
#define KS2 36
#define VS2 68
#define OFF_K0 2304
#define OFF_K1 4608
#define OFF_V0 6912
#define OFF_V1 9088
#define SMEM_ATTN (11264 * 4)   // 45056 B

__global__ __launch_bounds__(128, 4)
void attn_tc(const float* __restrict__ Q, const float* __restrict__ K,
             const float* __restrict__ Vt, const int* __restrict__ mask,
             const float* __restrict__ adjm, float* __restrict__ Xo)
{
    extern __shared__ float sm[];
    float* Qs = sm;                                   // [64][36]
    const int kOff[2] = { OFF_K0, OFF_K1 };
    const int vOff[2] = { OFF_V0, OFF_V1 };

    const unsigned sbase = (unsigned)__cvta_generic_to_shared(sm);

    const int tid = threadIdx.x, lane = tid & 31, w = tid >> 5;   // w in 0..3
    const int g = lane >> 2, t = lane & 3;

    const int bid = blockIdx.x;
    const int h  = bid & 3;
    const int qp = (bid >> 2) & 7;
    const int bt = bid >> 5;
    const size_t nb = (size_t)bt * Nn;
    const int n0 = qp * 64;

    const size_t vbase = ((size_t)(bt * 4 + h) * 32) * 512;   // Vt block for this (bt,h)

    // ---- stage Q block (64x32, raw copy: already tf32 bits) ----
    #pragma unroll
    for (int i = 0; i < 4; i++) {
        int idx = i * 128 + tid;
        int r = idx >> 3, seg = idx & 7;
        cpa16(sbase + (unsigned)((r * QS2 + seg * 4) * 4),
              Q + (nb + n0 + r) * DIMM + h * DK + seg * 4);
    }
    CP_COMMIT();

    // ---- prologue: stage K/V chunk 0 ----
    #pragma unroll
    for (int i = 0; i < 4; i++) {
        int idx = i * 128 + tid;
        int r = idx >> 3, seg = idx & 7;
        cpa16(sbase + (unsigned)((OFF_K0 + r * KS2 + seg * 4) * 4),
              K + (nb + r) * DIMM + h * DK + seg * 4);
    }
    #pragma unroll
    for (int i = 0; i < 4; i++) {
        int idx = i * 128 + tid;
        int dr = idx >> 4, seg = idx & 15;
        cpa16(sbase + (unsigned)((OFF_V0 + dr * VS2 + seg * 4) * 4),
              Vt + vbase + (size_t)dr * 512 + seg * 4);
    }
    CP_COMMIT();

    float oacc[4][4];
    #pragma unroll
    for (int nt = 0; nt < 4; nt++)
        #pragma unroll
        for (int c = 0; c < 4; c++) oacc[nt][c] = 0.f;

    float m0 = -1e30f, m1 = -1e30f, l0 = 0.f, l1 = 0.f;

    const int qrow0 = n0 + 16 * w + g;
    const size_t mrb0 = (nb + qrow0) * (size_t)Nn;
    const size_t mrb1 = mrb0 + 8 * (size_t)Nn;

    // shfl source lanes for PV A-frag construction
    const int s0 = 4 * g + (t >> 1);
    const int s1 = s0 + 2;
    const bool todd = (t & 1);

    const float scale = 0.17677669529663687f;

    for (int c = 0; c < 8; c++) {
        CP_WAIT0();          // chunk c (and Q on c==0) resident
        __syncthreads();     // visible to all; all warps done with chunk c-1 compute

        // ---- issue cp.async for chunk c+1 into the other buffer ----
        if (c < 7) {
            const int ko = kOff[(c + 1) & 1], vo = vOff[(c + 1) & 1];
            #pragma unroll
            for (int i = 0; i < 4; i++) {
                int idx = i * 128 + tid;
                int r = idx >> 3, seg = idx & 7;
                cpa16(sbase + (unsigned)((ko + r * KS2 + seg * 4) * 4),
                      K + (nb + (c + 1) * 64 + r) * DIMM + h * DK + seg * 4);
            }
            #pragma unroll
            for (int i = 0; i < 4; i++) {
                int idx = i * 128 + tid;
                int dr = idx >> 4, seg = idx & 15;
                cpa16(sbase + (unsigned)((vo + dr * VS2 + seg * 4) * 4),
                      Vt + vbase + (size_t)dr * 512 + (c + 1) * 64 + seg * 4);
            }
            CP_COMMIT();
        }

        const float* Ks = sm + kOff[c & 1];
        const float* Vs = sm + vOff[c & 1];

        // ---- prefetch mask ----
        int2 mk0[8], mk1[8];
        const int colb = c * 64 + 2 * t;
        #pragma unroll
        for (int nt = 0; nt < 8; nt++) {
            int col = colb + 8 * nt;
            mk0[nt] = *(const int2*)(mask + mrb0 + col);
            mk1[nt] = *(const int2*)(mask + mrb1 + col);
        }

        // ---- S = Q Kc^T ----
        float sacc[8][4];
        #pragma unroll
        for (int nt = 0; nt < 8; nt++)
            #pragma unroll
            for (int cc = 0; cc < 4; cc++) sacc[nt][cc] = 0.f;

        #pragma unroll
        for (int ks = 0; ks < 4; ks++) {
            const float* qrow = Qs + (16 * w + g) * QS2 + ks * 8;
            unsigned a0 = __float_as_uint(qrow[t]);
            unsigned a1 = __float_as_uint(qrow[8 * QS2 + t]);
            unsigned a2 = __float_as_uint(qrow[t + 4]);
            unsigned a3 = __float_as_uint(qrow[8 * QS2 + t + 4]);
            #pragma unroll
            for (int nt = 0; nt < 8; nt++) {
                const float* brow = Ks + (8 * nt + g) * KS2 + ks * 8;
                mma8(sacc[nt], a0, a1, a2, a3,
                     __float_as_uint(brow[t]), __float_as_uint(brow[t + 4]));
            }
        }

        // ---- mask + row max; adjm loads issued as mask regs die ----
        float rmax0 = -1e30f, rmax1 = -1e30f;
        float2 ad0[8], ad1[8];
        #pragma unroll
        for (int nt = 0; nt < 8; nt++) {
            float v0 = sacc[nt][0] * scale; if (mk0[nt].x) v0 = -1e9f;
            float v1 = sacc[nt][1] * scale; if (mk0[nt].y) v1 = -1e9f;
            float v2 = sacc[nt][2] * scale; if (mk1[nt].x) v2 = -1e9f;
            float v3 = sacc[nt][3] * scale; if (mk1[nt].y) v3 = -1e9f;
            sacc[nt][0] = v0; sacc[nt][1] = v1; sacc[nt][2] = v2; sacc[nt][3] = v3;
            rmax0 = fmaxf(rmax0, fmaxf(v0, v1));
            rmax1 = fmaxf(rmax1, fmaxf(v2, v3));
            int col = colb + 8 * nt;
            ad0[nt] = *(const float2*)(adjm + mrb0 + col);
            ad1[nt] = *(const float2*)(adjm + mrb1 + col);
        }
        rmax0 = fmaxf(rmax0, __shfl_xor_sync(0xffffffffu, rmax0, 1));
        rmax0 = fmaxf(rmax0, __shfl_xor_sync(0xffffffffu, rmax0, 2));
        rmax1 = fmaxf(rmax1, __shfl_xor_sync(0xffffffffu, rmax1, 1));
        rmax1 = fmaxf(rmax1, __shfl_xor_sync(0xffffffffu, rmax1, 2));

        float nm0 = fmaxf(m0, rmax0), nm1 = fmaxf(m1, rmax1);
        float al0 = __expf(m0 - nm0), al1 = __expf(m1 - nm1);
        m0 = nm0; m1 = nm1;

        // ---- P = exp(S-m)*adjm, stored IN-PLACE into sacc (tf32 bits) ----
        float rs0 = 0.f, rs1 = 0.f;
        #pragma unroll
        for (int nt = 0; nt < 8; nt++) {
            float p0 = __expf(sacc[nt][0] - nm0);
            float p1 = __expf(sacc[nt][1] - nm0);
            float p2 = __expf(sacc[nt][2] - nm1);
            float p3 = __expf(sacc[nt][3] - nm1);
            rs0 += p0 + p1; rs1 += p2 + p3;
            sacc[nt][0] = __uint_as_float(f2tf32u(p0 * ad0[nt].x));   // P[g   ][2t  ]
            sacc[nt][1] = __uint_as_float(f2tf32u(p1 * ad0[nt].y));   // P[g   ][2t+1]
            sacc[nt][2] = __uint_as_float(f2tf32u(p2 * ad1[nt].x));   // P[g+8 ][2t  ]
            sacc[nt][3] = __uint_as_float(f2tf32u(p3 * ad1[nt].y));   // P[g+8 ][2t+1]
        }
        rs0 += __shfl_xor_sync(0xffffffffu, rs0, 1);
        rs0 += __shfl_xor_sync(0xffffffffu, rs0, 2);
        rs1 += __shfl_xor_sync(0xffffffffu, rs1, 1);
        rs1 += __shfl_xor_sync(0xffffffffu, rs1, 2);
        l0 = l0 * al0 + rs0;
        l1 = l1 * al1 + rs1;

        #pragma unroll
        for (int nt = 0; nt < 4; nt++) {
            oacc[nt][0] *= al0; oacc[nt][1] *= al0;
            oacc[nt][2] *= al1; oacc[nt][3] *= al1;
        }

        // ---- O += P Vc : A-frags via lane shuffles (P bits live in sacc) ----
        #pragma unroll
        for (int kb = 0; kb < 8; kb++) {
            unsigned x0 = __shfl_sync(0xffffffffu, __float_as_uint(sacc[kb][0]), s0);
            unsigned x1 = __shfl_sync(0xffffffffu, __float_as_uint(sacc[kb][1]), s0);
            unsigned y0 = __shfl_sync(0xffffffffu, __float_as_uint(sacc[kb][2]), s0);
            unsigned y1 = __shfl_sync(0xffffffffu, __float_as_uint(sacc[kb][3]), s0);
            unsigned z0 = __shfl_sync(0xffffffffu, __float_as_uint(sacc[kb][0]), s1);
            unsigned z1 = __shfl_sync(0xffffffffu, __float_as_uint(sacc[kb][1]), s1);
            unsigned w0 = __shfl_sync(0xffffffffu, __float_as_uint(sacc[kb][2]), s1);
            unsigned w1 = __shfl_sync(0xffffffffu, __float_as_uint(sacc[kb][3]), s1);
            unsigned a0 = todd ? x1 : x0;   // P[g   ][8kb + t  ]
            unsigned a1 = todd ? y1 : y0;   // P[g+8 ][8kb + t  ]
            unsigned a2 = todd ? z1 : z0;   // P[g   ][8kb + t+4]
            unsigned a3 = todd ? w1 : w0;   // P[g+8 ][8kb + t+4]
            #pragma unroll
            for (int nt = 0; nt < 4; nt++) {
                const float* vrow = Vs + (8 * nt + g) * VS2 + kb * 8;
                mma8(oacc[nt], a0, a1, a2, a3,
                     __float_as_uint(vrow[t]), __float_as_uint(vrow[t + 4]));
            }
        }
        __syncthreads();   // all warps done with buffer c before it is refilled
    }

    // ---- epilogue ----
    float inv0 = 1.f / l0, inv1 = 1.f / l1;
    #pragma unroll
    for (int nt = 0; nt < 4; nt++) {
        float2 o0 = make_float2(oacc[nt][0] * inv0, oacc[nt][1] * inv0);
        float2 o1 = make_float2(oacc[nt][2] * inv1, oacc[nt][3] * inv1);
        *(float2*)(Xo + (nb + qrow0) * DIMM + h * DK + 8 * nt + 2 * t) = o0;
        *(float2*)(Xo + (nb + qrow0 + 8) * DIMM + h * DK + 8 * nt + 2 * t) = o1;
    }
}

// ---------------- launcher ----------------
extern "C" void kernel_launch(void* const* d_in, const int* in_sizes, int n_in,
                              void* d_out, int out_size)
{
    const float* query = (const float*)d_in[0];
    const float* key   = (const float*)d_in[1];
    const float* value = (const float*)d_in[2];
    const int*   mask  = (const int*)  d_in[3];
    const float* adjm  = (const float*)d_in[4];
    const float* Wq    = (const float*)d_in[5];
    const float* bq    = (const float*)d_in[6];
    const float* Wk    = (const float*)d_in[7];
    const float* bk    = (const float*)d_in[8];
    const float* Wv    = (const float*)d_in[9];
    const float* bv    = (const float*)d_in[10];
    const float* Wp    = (const float*)d_in[11];
    const float* bp    = (const float*)d_in[12];

    float *pQ, *pK, *pV, *pX;
    cudaGetSymbolAddress((void**)&pQ, g_Q);
    cudaGetSymbolAddress((void**)&pK, g_K);
    cudaGetSymbolAddress((void**)&pV, g_V);
    cudaGetSymbolAddress((void**)&pX, g_X);

    cudaFuncSetAttribute(gemm_tc, cudaFuncAttributeMaxDynamicSharedMemorySize, SMEM_GEMM);
    cudaFuncSetAttribute(attn_tc, cudaFuncAttributeMaxDynamicSharedMemorySize, SMEM_ATTN);

    // Q,K: tf32-rounded (mode 1); V: tf32-rounded + transposed (mode 2)
    gemm_tc<<<dim3(ROWS / 128, 3), 256, SMEM_GEMM>>>(
        query, Wq, bq, pQ,
        key,   Wk, bk, pK,
        value, Wv, bv, pV,
        1, 1, 2);

    attn_tc<<<Bb * Tt * 8 * 4, 128, SMEM_ATTN>>>(pQ, pK, pV, mask, adjm, pX);

    // out-proj: plain fp32 (mode 0)
    gemm_tc<<<dim3(ROWS / 128, 1), 256, SMEM_GEMM>>>(
        pX, Wp, bp, (float*)d_out,
        pX, Wp, bp, (float*)d_out,
        pX, Wp, bp, (float*)d_out,
        0, 0, 0);
}

// round 13
// speedup vs baseline: 1.4693x; 1.0354x over previous
#include <cuda_runtime.h>
#include <cstdint>

#define Bb   4
#define Tt   12
#define Nn   512
#define DIMM 128
#define DK   32
#define ROWS (Bb*Tt*Nn)          // 24576
#define NELEM (Bb*Tt*Nn*Nn)      // 12582912

// ---------------- scratch ----------------
__device__ float g_Q[ROWS * DIMM];           // tf32-rounded, [row][dim]
__device__ float g_K[ROWS * DIMM];           // tf32-rounded, [row][dim]
__device__ float g_V[ROWS * DIMM];           // tf32-rounded, TRANSPOSED [bt][h][d][kv]
__device__ float g_X[ROWS * DIMM];           // fp32 attn output
__device__ float g_A[NELEM];                 // packed adjm'' = mask ? -1 : adjm

// ---------------- helpers ----------------
__device__ __forceinline__ float f2tf32(float x) {
    unsigned u;
    asm("cvt.rna.tf32.f32 %0, %1;" : "=r"(u) : "f"(x));
    return __uint_as_float(u);
}
__device__ __forceinline__ unsigned f2tf32u(float x) {
    unsigned u;
    asm("cvt.rna.tf32.f32 %0, %1;" : "=r"(u) : "f"(x));
    return u;
}

__device__ __forceinline__ void mma8(float* c,
                                     unsigned a0, unsigned a1, unsigned a2, unsigned a3,
                                     unsigned b0, unsigned b1) {
    asm volatile(
        "mma.sync.aligned.m16n8k8.row.col.f32.tf32.tf32.f32 "
        "{%0,%1,%2,%3}, {%4,%5,%6,%7}, {%8,%9}, {%0,%1,%2,%3};"
        : "+f"(c[0]), "+f"(c[1]), "+f"(c[2]), "+f"(c[3])
        : "r"(a0), "r"(a1), "r"(a2), "r"(a3), "r"(b0), "r"(b1));
}

__device__ __forceinline__ void cpa16(unsigned dst, const void* src) {
    asm volatile("cp.async.cg.shared.global [%0], [%1], 16;" :: "r"(dst), "l"(src));
}
#define CP_COMMIT() asm volatile("cp.async.commit_group;")
#define CP_WAIT0()  asm volatile("cp.async.wait_group 0;")

// ================= GEMM (+ adjm packing slice at blockIdx.y==3) =================
// mode 0: fp32 out; 1: tf32 out; 2: tf32 + V-transposed out
#define GS 72
#define SMEM_GEMM (2 * 128 * GS * 4)

__global__ __launch_bounds__(256, 2)
void gemm_tc(const float* __restrict__ x0, const float* __restrict__ w0,
             const float* __restrict__ bb0, float* __restrict__ y0,
             const float* __restrict__ x1, const float* __restrict__ w1,
             const float* __restrict__ bb1, float* __restrict__ y1,
             const float* __restrict__ x2, const float* __restrict__ w2,
             const float* __restrict__ bb2, float* __restrict__ y2,
             int md0, int md1, int md2,
             const int* __restrict__ maskg, const float* __restrict__ adjg,
             float* __restrict__ packg)
{
    extern __shared__ float sm[];
    const int tid = threadIdx.x;

    // ---- packing slice: adjm'' = mask ? -1 : adjm ----
    if (blockIdx.y == 3) {
        const int4*   mk = (const int4*)maskg;
        const float4* ad = (const float4*)adjg;
        float4*       out = (float4*)packg;
        size_t base = (size_t)blockIdx.x * 16384 + tid;   // float4 units
        #pragma unroll 4
        for (int i = 0; i < 64; i++) {
            size_t p = base + (size_t)i * 256;
            int4 m = mk[p];
            float4 a = ad[p];
            if (m.x) a.x = -1.f;
            if (m.y) a.y = -1.f;
            if (m.z) a.z = -1.f;
            if (m.w) a.w = -1.f;
            out[p] = a;
        }
        return;
    }

    float* Xs = sm;               // [128][72]
    float* Ws = sm + 128 * GS;    // [128][72]

    const float* X = x0; const float* W = w0; const float* bias = bb0; float* Y = y0;
    int mode = md0;
    if (blockIdx.y == 1) { X = x1; W = w1; bias = bb1; Y = y1; mode = md1; }
    else if (blockIdx.y == 2) { X = x2; W = w2; bias = bb2; Y = y2; mode = md2; }

    const int lane = tid & 31, w = tid >> 5;
    const int g = lane >> 2, t = lane & 3;
    const size_t row0 = (size_t)blockIdx.x * 128;

    const int mrow0 = (w >> 1) * 32;
    const int e0    = (w & 1) * 64;

    float acc[2][8][4];
    #pragma unroll
    for (int mt = 0; mt < 2; mt++)
        #pragma unroll
        for (int nt = 0; nt < 8; nt++)
            #pragma unroll
            for (int c = 0; c < 4; c++) acc[mt][nt][c] = 0.f;

    for (int kh = 0; kh < 2; kh++) {
        if (kh) __syncthreads();
        #pragma unroll
        for (int i = 0; i < 8; i++) {
            int idx = i * 256 + tid;
            int r = idx >> 4, c4 = idx & 15;
            float4 xv = *(const float4*)(X + (row0 + r) * DIMM + kh * 64 + c4 * 4);
            float4 wv = *(const float4*)(W + (size_t)r * DIMM + kh * 64 + c4 * 4);
            int kb = c4 * 4;
            int base = kb & ~7, off = (kb & 4) ? 1 : 0;
            float* xd = Xs + r * GS + base + off;
            xd[0] = f2tf32(xv.x); xd[2] = f2tf32(xv.y);
            xd[4] = f2tf32(xv.z); xd[6] = f2tf32(xv.w);
            float* wd = Ws + r * GS + base + off;
            wd[0] = f2tf32(wv.x); wd[2] = f2tf32(wv.y);
            wd[4] = f2tf32(wv.z); wd[6] = f2tf32(wv.w);
        }
        __syncthreads();

        #pragma unroll
        for (int ks = 0; ks < 8; ks++) {
            uint2 aL[2], aH[2];
            #pragma unroll
            for (int mt = 0; mt < 2; mt++) {
                const float* ap = Xs + (mrow0 + 16 * mt + g) * GS + ks * 8 + 2 * t;
                aL[mt] = *(const uint2*)ap;
                aH[mt] = *(const uint2*)(ap + 8 * GS);
            }
            #pragma unroll
            for (int nt = 0; nt < 8; nt++) {
                uint2 b = *(const uint2*)(Ws + (e0 + 8 * nt + g) * GS + ks * 8 + 2 * t);
                mma8(acc[0][nt], aL[0].x, aH[0].x, aL[0].y, aH[0].y, b.x, b.y);
                mma8(acc[1][nt], aL[1].x, aH[1].x, aL[1].y, aH[1].y, b.x, b.y);
            }
        }
    }

    #pragma unroll
    for (int nt = 0; nt < 8; nt++) {
        float2 bv = *(const float2*)(bias + e0 + 8 * nt + 2 * t);
        const int e = e0 + 8 * nt + 2 * t;
        #pragma unroll
        for (int mt = 0; mt < 2; mt++) {
            size_t r0 = row0 + mrow0 + 16 * mt + g;
            float v00 = acc[mt][nt][0] + bv.x, v01 = acc[mt][nt][1] + bv.y;
            float v10 = acc[mt][nt][2] + bv.x, v11 = acc[mt][nt][3] + bv.y;
            if (mode == 0) {
                *(float2*)(Y + r0 * DIMM + e) = make_float2(v00, v01);
                *(float2*)(Y + (r0 + 8) * DIMM + e) = make_float2(v10, v11);
            } else if (mode == 1) {
                *(float2*)(Y + r0 * DIMM + e) = make_float2(f2tf32(v00), f2tf32(v01));
                *(float2*)(Y + (r0 + 8) * DIMM + e) = make_float2(f2tf32(v10), f2tf32(v11));
            } else {
                int bt = (int)(r0 >> 9);
                int kv = (int)(r0 & 511);
                int dl = e & 31;
                size_t base = ((size_t)(bt * 4 + (e >> 5)) * 32) * 512;
                Y[base + (size_t)dl * 512 + kv]           = f2tf32(v00);
                Y[base + (size_t)(dl + 1) * 512 + kv]     = f2tf32(v01);
                Y[base + (size_t)dl * 512 + kv + 8]       = f2tf32(v10);
                Y[base + (size_t)(dl + 1) * 512 + kv + 8] = f2tf32(v11);
            }
        }
    }
}

// ================= Flash attention (packed adjm'', deferred mask, Q in regs) =========
#define QS2 36
#define KS2 36
#define VS2 68
#define OFF_K0 2304
#define OFF_K1 4608
#define OFF_V0 6912
#define OFF_V1 9088
#define SMEM_ATTN (11264 * 4)   // 45056 B -> 4 CTAs/SM

__global__ __launch_bounds__(128, 4)
void attn_tc(const float* __restrict__ Q, const float* __restrict__ K,
             const float* __restrict__ Vt, const float* __restrict__ adjp,
             float* __restrict__ Xo)
{
    extern __shared__ float sm[];
    float* Qs = sm;                                   // [64][36]
    const int kOff[2] = { OFF_K0, OFF_K1 };
    const int vOff[2] = { OFF_V0, OFF_V1 };

    const unsigned sbase = (unsigned)__cvta_generic_to_shared(sm);

    const int tid = threadIdx.x, lane = tid & 31, w = tid >> 5;   // w in 0..3
    const int g = lane >> 2, t = lane & 3;

    const int bid = blockIdx.x;
    const int h  = bid & 3;
    const int qp = (bid >> 2) & 7;
    const int bt = bid >> 5;
    const size_t nb = (size_t)bt * Nn;
    const int n0 = qp * 64;

    const size_t vbase = ((size_t)(bt * 4 + h) * 32) * 512;

    // ---- stage Q block (64x32, raw copy) ----
    #pragma unroll
    for (int i = 0; i < 4; i++) {
        int idx = i * 128 + tid;
        int r = idx >> 3, seg = idx & 7;
        cpa16(sbase + (unsigned)((r * QS2 + seg * 4) * 4),
              Q + (nb + n0 + r) * DIMM + h * DK + seg * 4);
    }
    CP_COMMIT();

    // ---- stage K/V chunk 0 ----
    #pragma unroll
    for (int i = 0; i < 4; i++) {
        int idx = i * 128 + tid;
        int r = idx >> 3, seg = idx & 7;
        cpa16(sbase + (unsigned)((OFF_K0 + r * KS2 + seg * 4) * 4),
              K + (nb + r) * DIMM + h * DK + seg * 4);
    }
    #pragma unroll
    for (int i = 0; i < 4; i++) {
        int idx = i * 128 + tid;
        int dr = idx >> 4, seg = idx & 15;
        cpa16(sbase + (unsigned)((OFF_V0 + dr * VS2 + seg * 4) * 4),
              Vt + vbase + (size_t)dr * 512 + seg * 4);
    }
    CP_COMMIT();

    float oacc[4][4];
    #pragma unroll
    for (int nt = 0; nt < 4; nt++)
        #pragma unroll
        for (int c = 0; c < 4; c++) oacc[nt][c] = 0.f;

    float m0 = -1e30f, m1 = -1e30f, l0 = 0.f, l1 = 0.f;

    const int qrow0 = n0 + 16 * w + g;
    const size_t mrb0 = (nb + qrow0) * (size_t)Nn;
    const size_t mrb1 = mrb0 + 8 * (size_t)Nn;

    const int s0 = 4 * g + (t >> 1);
    const int s1 = s0 + 2;
    const bool todd = (t & 1);

    const float scale = 0.17677669529663687f;

    CP_WAIT0();          // Q + chunk 0 resident
    __syncthreads();

    // ---- hoist Q fragments into registers (chunk-invariant) ----
    unsigned qf[4][4];
    #pragma unroll
    for (int ks = 0; ks < 4; ks++) {
        const float* qrow = Qs + (16 * w + g) * QS2 + ks * 8;
        qf[ks][0] = __float_as_uint(qrow[t]);
        qf[ks][1] = __float_as_uint(qrow[8 * QS2 + t]);
        qf[ks][2] = __float_as_uint(qrow[t + 4]);
        qf[ks][3] = __float_as_uint(qrow[8 * QS2 + t + 4]);
    }

    for (int c = 0; c < 8; c++) {
        // ---- issue cp.async for chunk c+1 ----
        if (c < 7) {
            const int ko = kOff[(c + 1) & 1], vo = vOff[(c + 1) & 1];
            #pragma unroll
            for (int i = 0; i < 4; i++) {
                int idx = i * 128 + tid;
                int r = idx >> 3, seg = idx & 7;
                cpa16(sbase + (unsigned)((ko + r * KS2 + seg * 4) * 4),
                      K + (nb + (c + 1) * 64 + r) * DIMM + h * DK + seg * 4);
            }
            #pragma unroll
            for (int i = 0; i < 4; i++) {
                int idx = i * 128 + tid;
                int dr = idx >> 4, seg = idx & 15;
                cpa16(sbase + (unsigned)((vo + dr * VS2 + seg * 4) * 4),
                      Vt + vbase + (size_t)dr * 512 + (c + 1) * 64 + seg * 4);
            }
            CP_COMMIT();
        }

        const float* Ks = sm + kOff[c & 1];
        const float* Vs = sm + vOff[c & 1];

        // ---- prefetch packed adjm'' (single tensor: half the old traffic) ----
        float2 ad0[8], ad1[8];
        const int colb = c * 64 + 2 * t;
        #pragma unroll
        for (int nt = 0; nt < 8; nt++) {
            int col = colb + 8 * nt;
            ad0[nt] = *(const float2*)(adjp + mrb0 + col);
            ad1[nt] = *(const float2*)(adjp + mrb1 + col);
        }

        // ---- S = Q Kc^T ----
        float sacc[8][4];
        #pragma unroll
        for (int nt = 0; nt < 8; nt++)
            #pragma unroll
            for (int cc = 0; cc < 4; cc++) sacc[nt][cc] = 0.f;

        #pragma unroll
        for (int ks = 0; ks < 4; ks++) {
            #pragma unroll
            for (int nt = 0; nt < 8; nt++) {
                const float* brow = Ks + (8 * nt + g) * KS2 + ks * 8;
                mma8(sacc[nt], qf[ks][0], qf[ks][1], qf[ks][2], qf[ks][3],
                     __float_as_uint(brow[t]), __float_as_uint(brow[t + 4]));
            }
        }

        // ---- row max over RAW scores (mask deferred; cancels exactly) ----
        float rmax0 = -1e30f, rmax1 = -1e30f;
        #pragma unroll
        for (int nt = 0; nt < 8; nt++) {
            float v0 = sacc[nt][0] * scale;
            float v1 = sacc[nt][1] * scale;
            float v2 = sacc[nt][2] * scale;
            float v3 = sacc[nt][3] * scale;
            sacc[nt][0] = v0; sacc[nt][1] = v1; sacc[nt][2] = v2; sacc[nt][3] = v3;
            rmax0 = fmaxf(rmax0, fmaxf(v0, v1));
            rmax1 = fmaxf(rmax1, fmaxf(v2, v3));
        }
        rmax0 = fmaxf(rmax0, __shfl_xor_sync(0xffffffffu, rmax0, 1));
        rmax0 = fmaxf(rmax0, __shfl_xor_sync(0xffffffffu, rmax0, 2));
        rmax1 = fmaxf(rmax1, __shfl_xor_sync(0xffffffffu, rmax1, 1));
        rmax1 = fmaxf(rmax1, __shfl_xor_sync(0xffffffffu, rmax1, 2));

        float nm0 = fmaxf(m0, rmax0), nm1 = fmaxf(m1, rmax1);
        float al0 = __expf(m0 - nm0), al1 = __expf(m1 - nm1);
        m0 = nm0; m1 = nm1;

        // ---- P: e zeroed where adjm''<0; stored IN-PLACE into sacc (tf32 bits) ----
        float rs0 = 0.f, rs1 = 0.f;
        #pragma unroll
        for (int nt = 0; nt < 8; nt++) {
            float e0 = __expf(sacc[nt][0] - nm0);
            float e1 = __expf(sacc[nt][1] - nm0);
            float e2 = __expf(sacc[nt][2] - nm1);
            float e3 = __expf(sacc[nt][3] - nm1);
            if (ad0[nt].x < 0.f) e0 = 0.f;
            if (ad0[nt].y < 0.f) e1 = 0.f;
            if (ad1[nt].x < 0.f) e2 = 0.f;
            if (ad1[nt].y < 0.f) e3 = 0.f;
            rs0 += e0 + e1; rs1 += e2 + e3;
            sacc[nt][0] = __uint_as_float(f2tf32u(e0 * ad0[nt].x));
            sacc[nt][1] = __uint_as_float(f2tf32u(e1 * ad0[nt].y));
            sacc[nt][2] = __uint_as_float(f2tf32u(e2 * ad1[nt].x));
            sacc[nt][3] = __uint_as_float(f2tf32u(e3 * ad1[nt].y));
        }
        rs0 += __shfl_xor_sync(0xffffffffu, rs0, 1);
        rs0 += __shfl_xor_sync(0xffffffffu, rs0, 2);
        rs1 += __shfl_xor_sync(0xffffffffu, rs1, 1);
        rs1 += __shfl_xor_sync(0xffffffffu, rs1, 2);
        l0 = l0 * al0 + rs0;
        l1 = l1 * al1 + rs1;

        #pragma unroll
        for (int nt = 0; nt < 4; nt++) {
            oacc[nt][0] *= al0; oacc[nt][1] *= al0;
            oacc[nt][2] *= al1; oacc[nt][3] *= al1;
        }

        // ---- O += P Vc : A-frags via lane shuffles ----
        #pragma unroll
        for (int kb = 0; kb < 8; kb++) {
            unsigned x0 = __shfl_sync(0xffffffffu, __float_as_uint(sacc[kb][0]), s0);
            unsigned x1 = __shfl_sync(0xffffffffu, __float_as_uint(sacc[kb][1]), s0);
            unsigned y0 = __shfl_sync(0xffffffffu, __float_as_uint(sacc[kb][2]), s0);
            unsigned y1 = __shfl_sync(0xffffffffu, __float_as_uint(sacc[kb][3]), s0);
            unsigned z0 = __shfl_sync(0xffffffffu, __float_as_uint(sacc[kb][0]), s1);
            unsigned z1 = __shfl_sync(0xffffffffu, __float_as_uint(sacc[kb][1]), s1);
            unsigned w0 = __shfl_sync(0xffffffffu, __float_as_uint(sacc[kb][2]), s1);
            unsigned w1 = __shfl_sync(0xffffffffu, __float_as_uint(sacc[kb][3]), s1);
            unsigned a0 = todd ? x1 : x0;
            unsigned a1 = todd ? y1 : y0;
            unsigned a2 = todd ? z1 : z0;
            unsigned a3 = todd ? w1 : w0;
            #pragma unroll
            for (int nt = 0; nt < 4; nt++) {
                const float* vrow = Vs + (8 * nt + g) * VS2 + kb * 8;
                mma8(oacc[nt], a0, a1, a2, a3,
                     __float_as_uint(vrow[t]), __float_as_uint(vrow[t + 4]));
            }
        }

        if (c < 7) {
            CP_WAIT0();
            __syncthreads();   // chunk c+1 resident; buffer c reusable
        }
    }

    // ---- epilogue ----
    float inv0 = 1.f / l0, inv1 = 1.f / l1;
    #pragma unroll
    for (int nt = 0; nt < 4; nt++) {
        float2 o0 = make_float2(oacc[nt][0] * inv0, oacc[nt][1] * inv0);
        float2 o1 = make_float2(oacc[nt][2] * inv1, oacc[nt][3] * inv1);
        *(float2*)(Xo + (nb + qrow0) * DIMM + h * DK + 8 * nt + 2 * t) = o0;
        *(float2*)(Xo + (nb + qrow0 + 8) * DIMM + h * DK + 8 * nt + 2 * t) = o1;
    }
}

// ---------------- launcher ----------------
extern "C" void kernel_launch(void* const* d_in, const int* in_sizes, int n_in,
                              void* d_out, int out_size)
{
    const float* query = (const float*)d_in[0];
    const float* key   = (const float*)d_in[1];
    const float* value = (const float*)d_in[2];
    const int*   mask  = (const int*)  d_in[3];
    const float* adjm  = (const float*)d_in[4];
    const float* Wq    = (const float*)d_in[5];
    const float* bq    = (const float*)d_in[6];
    const float* Wk    = (const float*)d_in[7];
    const float* bk    = (const float*)d_in[8];
    const float* Wv    = (const float*)d_in[9];
    const float* bv    = (const float*)d_in[10];
    const float* Wp    = (const float*)d_in[11];
    const float* bp    = (const float*)d_in[12];

    float *pQ, *pK, *pV, *pX, *pA;
    cudaGetSymbolAddress((void**)&pQ, g_Q);
    cudaGetSymbolAddress((void**)&pK, g_K);
    cudaGetSymbolAddress((void**)&pV, g_V);
    cudaGetSymbolAddress((void**)&pX, g_X);
    cudaGetSymbolAddress((void**)&pA, g_A);

    cudaFuncSetAttribute(gemm_tc, cudaFuncAttributeMaxDynamicSharedMemorySize, SMEM_GEMM);
    cudaFuncSetAttribute(attn_tc, cudaFuncAttributeMaxDynamicSharedMemorySize, SMEM_ATTN);

    // y=0..2: QKV projections; y=3: adjm packing (overlapped)
    gemm_tc<<<dim3(ROWS / 128, 4), 256, SMEM_GEMM>>>(
        query, Wq, bq, pQ,
        key,   Wk, bk, pK,
        value, Wv, bv, pV,
        1, 1, 2,
        mask, adjm, pA);

    attn_tc<<<Bb * Tt * 8 * 4, 128, SMEM_ATTN>>>(pQ, pK, pV, pA, pX);

    gemm_tc<<<dim3(ROWS / 128, 1), 256, SMEM_GEMM>>>(
        pX, Wp, bp, (float*)d_out,
        pX, Wp, bp, (float*)d_out,
        pX, Wp, bp, (float*)d_out,
        0, 0, 0,
        (const int*)0, (const float*)0, (float*)0);
}